// round 6
// baseline (speedup 1.0000x reference)
#include <cuda_runtime.h>

// EfficientAttention fused kernel (sm_100a).
// R4/R5/R6: each (n,i) row split into TWO half-row CTAs (1024 CTAs x 320 thr),
// smem ~102KB/CTA -> occupancy 2 (phase overlap across co-resident CTAs) and
// finer wave tail (makespan 8->7 half-units). Conv inner loop = proven T=2
// f32x2 form. Circular-roll gather wrap at the half boundaries falls back to
// direct LDG (L2-hit) for the few edge values.
// (R6 is the second resubmit after repeated infra-side container failures.)

#define NTHR  320
#define QROW2 89           // 89 cols: logical j in [base-4, base+85); odd stride
#define KROW  52           // 50 K floats per c, padded
#define W_OFF1   5242880   // 4*128*160*64
#define W_OFF2   6062080   // W_OFF1 + 512*160*10

__device__ __forceinline__ unsigned long long pack2(float lo, float hi) {
    unsigned long long r;
    asm("mov.b64 %0, {%1, %2};" : "=l"(r) : "f"(lo), "f"(hi));
    return r;
}
__device__ __forceinline__ void unpack2(unsigned long long v, float& lo, float& hi) {
    asm("mov.b64 {%0, %1}, %2;" : "=f"(lo), "=f"(hi) : "l"(v));
}
__device__ __forceinline__ void fma2(unsigned long long& d, unsigned long long a,
                                     unsigned long long b) {
    asm("fma.rn.f32x2 %0, %1, %2, %3;" : "=l"(d) : "l"(a), "l"(b), "l"(d));
}

// Gather read: smem when jlog is inside this CTA's loaded window, else gmem (L2).
__device__ __forceinline__ float getQ(const float* colbase_s, const float* row_g,
                                      int k, int jlog, int loJ) {
    if ((unsigned)(jlog - loJ) < (unsigned)QROW2)
        return colbase_s[jlog - loJ];
    return row_g[jlog * 64 + k];
}

__global__ void __launch_bounds__(NTHR, 2)
ea_kernel(const float* __restrict__ gL, const float* __restrict__ gR,
          const float* __restrict__ gK, const float* __restrict__ gBias,
          const float* __restrict__ gGamma, const float* __restrict__ gBeta,
          const float* __restrict__ gMean, const float* __restrict__ gVar,
          float* __restrict__ out)
{
    extern __shared__ float sm[];
    float* Qt = sm;                        // 128*89 (L ch 0..63, R ch 64..127)
    float* Kc = Qt + 128 * QROW2;          // 128*52:  Kc[c][w*10+m]
    float* W4 = Kc + 128 * KROW;           // 8*80*11: per-group logit partials
    float* WS = W4 + 8 * 80 * 11;          // 80*12:   softmaxed weights

    const int t    = threadIdx.x;
    const int row  = blockIdx.x >> 1;      // n*H + i
    const int h    = blockIdx.x & 1;       // half: j base
    const int base = h * 80;
    const int loJ  = base - 4;             // logical j of Qt col 0

    const float* Lrow = gL + (size_t)row * (160 * 64);
    const float* Rrow = gR + (size_t)row * (160 * 64);

    // ---- zero SAME-conv padding cols (outside logical [0,160)) ----
    {
        const int npad = h ? 5 : 4;        // h=0: cols 0..3 ; h=1: cols 84..88
        const int pad0 = h ? 84 : 0;
        for (int z = t; z < 128 * 5; z += NTHR) {
            int c = z / 5, pc = z % 5;
            if (pc < npad) Qt[c * QROW2 + pad0 + pc] = 0.f;
        }
    }

    // ---- load valid j range (coalesced float4) -> transposed smem ----
    {
        const int jv0 = h ? 76 : 0;        // first valid logical j in window
        const int nv  = h ? 84 : 85;       // number of valid cols
        const int n4  = nv * 16;           // float4 count per input
        for (int i4 = t; i4 < n4; i4 += NTHR) {
            int jrel = i4 >> 4, c = (i4 & 15) << 2;
            int col  = (jv0 + jrel) - loJ;
            int gidx = jv0 * 16 + i4;
            float4 v = reinterpret_cast<const float4*>(Lrow)[gidx];
            Qt[(c + 0) * QROW2 + col] = v.x;
            Qt[(c + 1) * QROW2 + col] = v.y;
            Qt[(c + 2) * QROW2 + col] = v.z;
            Qt[(c + 3) * QROW2 + col] = v.w;
            float4 u = reinterpret_cast<const float4*>(Rrow)[gidx];
            Qt[(c + 64) * QROW2 + col] = u.x;
            Qt[(c + 65) * QROW2 + col] = u.y;
            Qt[(c + 66) * QROW2 + col] = u.z;
            Qt[(c + 67) * QROW2 + col] = u.w;
        }
    }

    // ---- load conv kernel, HWIO (w,c,m) -> Kc[c][w*10+m] ----
    #pragma unroll
    for (int kk = 0; kk < 20; kk++) {
        int g = t + kk * NTHR;             // 0..6399
        int m = g % 10;
        int c = (g / 10) & 127;
        int w = g / 1280;
        Kc[c * KROW + w * 10 + m] = gK[g];
    }
    __syncthreads();

    // ---- conv: thread = (j-pair of this half, c-group of 16 channels) ----
    {
        const int jp = t % 40;             // local j = 2*jp, 2*jp+1
        const int cg = t / 40;             // 0..7

        unsigned long long accA[5], accB[5];
        #pragma unroll
        for (int p = 0; p < 5; p++) { accA[p] = 0ull; accB[p] = 0ull; }

        // window cols for local jA=2jp: col = (base+2jp-2) - loJ = 2jp+2
        const float* qbase = Qt + (cg * 16) * QROW2 + 2 * jp + 2;
        const float* kbase = Kc + (cg * 16) * KROW;

        #pragma unroll 2
        for (int ci = 0; ci < 16; ci++) {
            const float* q = qbase + ci * QROW2;
            unsigned long long pk[6];
            pk[0] = pack2(q[0], q[0]); pk[1] = pack2(q[1], q[1]);
            pk[2] = pack2(q[2], q[2]); pk[3] = pack2(q[3], q[3]);
            pk[4] = pack2(q[4], q[4]); pk[5] = pack2(q[5], q[5]);

            const float* krow = kbase + ci * KROW;
            const ulonglong2* kp = reinterpret_cast<const ulonglong2*>(krow);
            #pragma unroll
            for (int i = 0; i < 12; i++) {
                ulonglong2 kv = kp[i];     // broadcast LDS.128
                const int pi0 = 2 * i, pi1 = 2 * i + 1;
                const int p0 = pi0 % 5, w0 = pi0 / 5;
                const int p1 = pi1 % 5, w1 = pi1 / 5;
                fma2(accA[p0], pk[w0],     kv.x);
                fma2(accB[p0], pk[w0 + 1], kv.x);
                fma2(accA[p1], pk[w1],     kv.y);
                fma2(accB[p1], pk[w1 + 1], kv.y);
            }
            unsigned long long kl =
                reinterpret_cast<const unsigned long long*>(krow)[24];
            fma2(accA[4], pk[4], kl);
            fma2(accB[4], pk[5], kl);
        }

        float* wdA = W4 + (cg * 80 + 2 * jp) * 11;
        float* wdB = wdA + 11;
        #pragma unroll
        for (int p = 0; p < 5; p++) {
            float lo, hi;
            unpack2(accA[p], lo, hi);
            wdA[2 * p] = lo; wdA[2 * p + 1] = hi;
            unpack2(accB[p], lo, hi);
            wdB[2 * p] = lo; wdB[2 * p + 1] = hi;
        }
    }
    __syncthreads();

    // ---- logit reduction + softmax + weight outputs (threads 0..79) ----
    if (t < 80) {
        float v[10];
        #pragma unroll
        for (int m = 0; m < 10; m++) {
            float a = gBias[m];
            #pragma unroll
            for (int g = 0; g < 8; g++)
                a += W4[(g * 80 + t) * 11 + m];
            v[m] = a;
        }
        float mx = v[0];
        #pragma unroll
        for (int m = 1; m < 10; m++) mx = fmaxf(mx, v[m]);
        float s = 0.f;
        #pragma unroll
        for (int m = 0; m < 10; m++) { float e = __expf(v[m] - mx); v[m] = e; s += e; }
        float inv = 1.f / s;
        float* wr = WS + t * 12;
        size_t wo = (size_t)row * 1600 + (size_t)(base + t) * 10;
        #pragma unroll
        for (int m = 0; m < 10; m++) {
            float wv = v[m] * inv;
            wr[m] = wv;
            out[W_OFF1 + wo + m] = wv;
            out[W_OFF2 + wo + m] = wv;
        }
    }
    __syncthreads();

    // ---- shiftmap gather + BN + tanh: thread = (k, group of 16 j) ----
    {
        const int k  = t & 63;
        const int g  = t >> 6;             // 0..4
        const int j0 = base + g * 16;      // global j start

        float sc = gGamma[k] / sqrtf(gVar[k] + 1e-3f);
        float sh = gBeta[k] - gMean[k] * sc;

        const float* Lc = Qt + k * QROW2;          // col 0 == logical loJ
        const float* Rc = Qt + (64 + k) * QROW2;

        float lw[5], rw[5];
        #pragma unroll
        for (int s = 0; s < 5; s++) {
            int li = j0 - s; if (li < 0) li += 160;
            lw[s] = getQ(Lc, Lrow, k, li, loJ);
            rw[s] = getQ(Rc, Rrow, k, j0 + s, loJ);   // j0+s <= 148, in [0,160)
        }

        float* xout = out + (size_t)(row * 160 + j0) * 64 + k;
        #pragma unroll
        for (int jj = 0; jj < 16; jj++) {
            int j = j0 + jj;
            const unsigned long long* wp =
                reinterpret_cast<const unsigned long long*>(WS + (j - base) * 12);
            unsigned long long a = 0ull;
            #pragma unroll
            for (int s = 0; s < 5; s++)
                fma2(a, wp[s], pack2(lw[s], rw[s]));
            float lo, hi;
            unpack2(a, lo, hi);
            float x = (lo + hi) * sc + sh;
            float e = __expf(2.f * x);     // tanh = 1 - 2/(e^{2x}+1)
            x = 1.f - 2.f / (e + 1.f);
            xout[(size_t)jj * 64] = x;

            int ln = j + 1; if (ln >= 160) ln -= 160;
            int rn = j + 5; if (rn >= 160) rn -= 160;
            lw[4] = lw[3]; lw[3] = lw[2]; lw[2] = lw[1]; lw[1] = lw[0];
            lw[0] = getQ(Lc, Lrow, k, ln, loJ);
            rw[0] = rw[1]; rw[1] = rw[2]; rw[2] = rw[3]; rw[3] = rw[4];
            rw[4] = getQ(Rc, Rrow, k, rn, loJ);
        }
    }
}

extern "C" void kernel_launch(void* const* d_in, const int* in_sizes, int n_in,
                              void* d_out, int out_size)
{
    const float* L     = (const float*)d_in[0];
    const float* R     = (const float*)d_in[1];
    const float* K     = (const float*)d_in[2];
    const float* bias  = (const float*)d_in[3];
    const float* gamma = (const float*)d_in[4];
    const float* beta  = (const float*)d_in[5];
    const float* mean  = (const float*)d_in[6];
    const float* var   = (const float*)d_in[7];
    float* out = (float*)d_out;

    const int smem = (128 * QROW2 + 128 * KROW + 8 * 80 * 11 + 80 * 12) * 4; // 104192 B
    cudaFuncSetAttribute(ea_kernel, cudaFuncAttributeMaxDynamicSharedMemorySize, smem);
    ea_kernel<<<1024, NTHR, smem>>>(L, R, K, bias, gamma, beta, mean, var, out);
}